// round 1
// baseline (speedup 1.0000x reference)
#include <cuda_runtime.h>

#define N_HW  262144      // 512*512
#define N_W   512
#define O_HW  65536       // 256*256
#define O_W   256
#define PI_F  3.14159265358979f

// 64 MB scratch for the grayscale image (sanctioned __device__-global scratch).
__device__ float    g_gray[(size_t)64 * N_HW];
__device__ unsigned g_min_ord, g_max_ord;
// packed constants:
// [0..7]  cos(w[l][q][0])   (l*4+q)
// [8..15] sin(w[l][q][1])
// [16..23] w[l][q][2]
// [24..39] proj_w[o][q]     (24 + o*4 + q)
// [40..43] proj_b[o]
// [44] = PI/range, [45] = -min*PI/range
__device__ float    g_c[48];

__device__ __forceinline__ unsigned f2ord(float f) {
    unsigned u = __float_as_uint(f);
    return (u & 0x80000000u) ? ~u : (u | 0x80000000u);
}
__device__ __forceinline__ float ord2f(unsigned o) {
    unsigned u = (o & 0x80000000u) ? (o & 0x7fffffffu) : ~o;
    return __uint_as_float(u);
}

__global__ void k_init(const float* __restrict__ w,
                       const float* __restrict__ pw,
                       const float* __restrict__ pb) {
    int t = threadIdx.x;
    if (t == 0) { g_min_ord = 0xffffffffu; g_max_ord = 0u; }
    if (t < 8) {
        int l = t >> 2, q = t & 3;
        const float* wi = w + l * 12 + q * 3;
        g_c[t]      = cosf(wi[0]);
        g_c[8 + t]  = sinf(wi[1]);
        g_c[16 + t] = wi[2];
    }
    if (t < 16) g_c[24 + t] = pw[t];
    if (t < 4)  g_c[40 + t] = pb[t];
}

// Pass 1: gray = mean(channels), stream out + global min/max reduction.
__global__ void k_gray(const float* __restrict__ x) {
    int idx = blockIdx.x * blockDim.x + threadIdx.x;   // float4 index into gray
    int b   = idx >> 16;                               // 65536 float4s per image
    int r4  = idx & 65535;
    const float4* xb = reinterpret_cast<const float4*>(x) + (size_t)b * (3 * N_HW / 4);
    float4 a = __ldg(xb + r4);
    float4 c = __ldg(xb + r4 + N_HW / 4);
    float4 d = __ldg(xb + r4 + N_HW / 2);
    const float k = 1.0f / 3.0f;
    float4 g;
    g.x = (a.x + c.x + d.x) * k;
    g.y = (a.y + c.y + d.y) * k;
    g.z = (a.z + c.z + d.z) * k;
    g.w = (a.w + c.w + d.w) * k;
    reinterpret_cast<float4*>(g_gray)[idx] = g;

    float lmin = fminf(fminf(g.x, g.y), fminf(g.z, g.w));
    float lmax = fmaxf(fmaxf(g.x, g.y), fmaxf(g.z, g.w));
    #pragma unroll
    for (int off = 16; off > 0; off >>= 1) {
        lmin = fminf(lmin, __shfl_xor_sync(0xffffffffu, lmin, off));
        lmax = fmaxf(lmax, __shfl_xor_sync(0xffffffffu, lmax, off));
    }
    __shared__ float smin[8], smax[8];
    int lane = threadIdx.x & 31, wid = threadIdx.x >> 5;
    if (lane == 0) { smin[wid] = lmin; smax[wid] = lmax; }
    __syncthreads();
    if (wid == 0) {
        lmin = (lane < 8) ? smin[lane] : __uint_as_float(0x7f800000u);  // +inf
        lmax = (lane < 8) ? smax[lane] : __uint_as_float(0xff800000u);  // -inf
        #pragma unroll
        for (int off = 4; off > 0; off >>= 1) {
            lmin = fminf(lmin, __shfl_xor_sync(0xffffffffu, lmin, off));
            lmax = fmaxf(lmax, __shfl_xor_sync(0xffffffffu, lmax, off));
        }
        if (lane == 0) {
            atomicMin(&g_min_ord, f2ord(lmin));
            atomicMax(&g_max_ord, f2ord(lmax));
        }
    }
}

__global__ void k_norm() {
    float mn  = ord2f(g_min_ord);
    float mx  = ord2f(g_max_ord);
    float inv = 1.0f / (mx - mn + 1e-8f);
    g_c[44] = inv * PI_F;
    g_c[45] = -mn * inv * PI_F;
}

// accurate-enough fast tanh: 2 MUFU (EX2 + RCP) + a few FMA. Avoids
// tanh.approx.f32's ~5e-4 abs error which could threaten rel_err<1e-3.
__device__ __forceinline__ float tanh_fast(float x) {
    x = fminf(15.0f, fmaxf(-15.0f, x));
    float e = __expf(2.0f * x);
    return (e - 1.0f) * __fdividef(1.0f, e + 1.0f);
}

// Pass 2: 4 output pixels per thread (amortizes the 12 constant LDG.128,
// makes gray reads float4 and output writes float4).
__global__ void __launch_bounds__(256) k_main(float* __restrict__ out) {
    int idx = blockIdx.x * blockDim.x + threadIdx.x;   // quad index
    int wq  = idx & 63;            // 64 quads per output row
    int h   = (idx >> 6) & 255;
    int b   = idx >> 14;

    float4 cc[12];
    #pragma unroll
    for (int i = 0; i < 12; i++)
        cc[i] = reinterpret_cast<const float4*>(g_c)[i];
    const float* gc = reinterpret_cast<const float*>(cc);
    float A = gc[44], Bc = gc[45];

    const float4* gr = reinterpret_cast<const float4*>(g_gray + (size_t)b * N_HW + (size_t)(2 * h) * N_W);
    float4 a0 = gr[2 * wq],             a1 = gr[2 * wq + 1];
    float4 b0 = gr[2 * wq + N_W / 4],   b1 = gr[2 * wq + 1 + N_W / 4];

    // patch layout per output pixel: {g[2h][2w], g[2h][2w+1], g[2h+1][2w], g[2h+1][2w+1]}
    float px[4][4] = {
        {a0.x, a0.y, b0.x, b0.y},
        {a0.z, a0.w, b0.z, b0.w},
        {a1.x, a1.y, b1.x, b1.y},
        {a1.z, a1.w, b1.z, b1.w}};

    float res[4][4];   // [o][pixel]
    #pragma unroll
    for (int j = 0; j < 4; j++) {
        float e[4];
        #pragma unroll
        for (int q = 0; q < 4; q++)
            e[q] = __sinf(fmaf(px[j][q], A, Bc));
        #pragma unroll
        for (int l = 0; l < 2; l++) {
            float m[4];
            #pragma unroll
            for (int q = 0; q < 4; q++)
                m[q] = fmaf(e[q], gc[l * 4 + q],
                       fmaf(e[(q + 1) & 3], gc[8 + l * 4 + q], gc[16 + l * 4 + q]));
            #pragma unroll
            for (int q = 0; q < 4; q++)
                e[q] = tanh_fast(m[q]);
        }
        #pragma unroll
        for (int o = 0; o < 4; o++)
            res[o][j] = fmaf(e[3], gc[24 + o * 4 + 3],
                        fmaf(e[2], gc[24 + o * 4 + 2],
                        fmaf(e[1], gc[24 + o * 4 + 1],
                        fmaf(e[0], gc[24 + o * 4 + 0], gc[40 + o]))));
    }

    size_t ob = (size_t)(b * 4) * O_HW + (size_t)h * O_W + (size_t)(wq * 4);
    #pragma unroll
    for (int o = 0; o < 4; o++)
        *reinterpret_cast<float4*>(out + ob + (size_t)o * O_HW) =
            make_float4(res[o][0], res[o][1], res[o][2], res[o][3]);
}

extern "C" void kernel_launch(void* const* d_in, const int* in_sizes, int n_in,
                              void* d_out, int out_size) {
    const float* x  = (const float*)d_in[0];   // (64,3,512,512)
    const float* w  = (const float*)d_in[1];   // (2,4,3)
    const float* pw = (const float*)d_in[2];   // (4,4,1,1)
    const float* pb = (const float*)d_in[3];   // (4,)
    float* out = (float*)d_out;                // (64,4,256,256)

    k_init<<<1, 32>>>(w, pw, pb);
    k_gray<<<16384, 256>>>(x);                 // 64*512*512/4 threads
    k_norm<<<1, 1>>>();
    k_main<<<4096, 256>>>(out);                // 64*256*256/4 threads
}

// round 2
// speedup vs baseline: 1.0155x; 1.0155x over previous
#include <cuda_runtime.h>

#define N_HW  262144      // 512*512
#define N_W   512
#define O_HW  65536       // 256*256
#define O_W   256
#define PI_F  3.14159265358979f

// 64 MB scratch for the grayscale image (sanctioned __device__-global scratch).
__device__ float    g_gray[(size_t)64 * N_HW];
__device__ unsigned g_min_ord, g_max_ord;
// packed constants:
// [0..7]  cos(w[l][q][0])   (l*4+q)
// [8..15] sin(w[l][q][1])
// [16..23] w[l][q][2]
// [24..39] proj_w[o][q]     (24 + o*4 + q)
// [40..43] proj_b[o]
// [44] = PI/range, [45] = -min*PI/range
__device__ float    g_c[48];

__device__ __forceinline__ unsigned f2ord(float f) {
    unsigned u = __float_as_uint(f);
    return (u & 0x80000000u) ? ~u : (u | 0x80000000u);
}
__device__ __forceinline__ float ord2f(unsigned o) {
    unsigned u = (o & 0x80000000u) ? (o & 0x7fffffffu) : ~o;
    return __uint_as_float(u);
}

__global__ void k_init(const float* __restrict__ w,
                       const float* __restrict__ pw,
                       const float* __restrict__ pb) {
    int t = threadIdx.x;
    if (t == 0) { g_min_ord = 0xffffffffu; g_max_ord = 0u; }
    if (t < 8) {
        int l = t >> 2, q = t & 3;
        const float* wi = w + l * 12 + q * 3;
        g_c[t]      = cosf(wi[0]);
        g_c[8 + t]  = sinf(wi[1]);
        g_c[16 + t] = wi[2];
    }
    if (t < 16) g_c[24 + t] = pw[t];
    if (t < 4)  g_c[40 + t] = pb[t];
}

// Pass 1: gray = mean(channels), stream out + global min/max reduction.
__global__ void k_gray(const float* __restrict__ x) {
    int idx = blockIdx.x * blockDim.x + threadIdx.x;   // float4 index into gray
    int b   = idx >> 16;                               // 65536 float4s per image
    int r4  = idx & 65535;
    const float4* xb = reinterpret_cast<const float4*>(x) + (size_t)b * (3 * N_HW / 4);
    float4 a = __ldg(xb + r4);
    float4 c = __ldg(xb + r4 + N_HW / 4);
    float4 d = __ldg(xb + r4 + N_HW / 2);
    const float k = 1.0f / 3.0f;
    float4 g;
    g.x = (a.x + c.x + d.x) * k;
    g.y = (a.y + c.y + d.y) * k;
    g.z = (a.z + c.z + d.z) * k;
    g.w = (a.w + c.w + d.w) * k;
    reinterpret_cast<float4*>(g_gray)[idx] = g;

    float lmin = fminf(fminf(g.x, g.y), fminf(g.z, g.w));
    float lmax = fmaxf(fmaxf(g.x, g.y), fmaxf(g.z, g.w));
    #pragma unroll
    for (int off = 16; off > 0; off >>= 1) {
        lmin = fminf(lmin, __shfl_xor_sync(0xffffffffu, lmin, off));
        lmax = fmaxf(lmax, __shfl_xor_sync(0xffffffffu, lmax, off));
    }
    __shared__ float smin[8], smax[8];
    int lane = threadIdx.x & 31, wid = threadIdx.x >> 5;
    if (lane == 0) { smin[wid] = lmin; smax[wid] = lmax; }
    __syncthreads();
    if (wid == 0) {
        lmin = (lane < 8) ? smin[lane] : __uint_as_float(0x7f800000u);  // +inf
        lmax = (lane < 8) ? smax[lane] : __uint_as_float(0xff800000u);  // -inf
        #pragma unroll
        for (int off = 4; off > 0; off >>= 1) {
            lmin = fminf(lmin, __shfl_xor_sync(0xffffffffu, lmin, off));
            lmax = fmaxf(lmax, __shfl_xor_sync(0xffffffffu, lmax, off));
        }
        if (lane == 0) {
            atomicMin(&g_min_ord, f2ord(lmin));
            atomicMax(&g_max_ord, f2ord(lmax));
        }
    }
}

__global__ void k_norm() {
    float mn  = ord2f(g_min_ord);
    float mx  = ord2f(g_max_ord);
    float inv = 1.0f / (mx - mn + 1e-8f);
    g_c[44] = inv * PI_F;
    g_c[45] = -mn * inv * PI_F;
}

// accurate-enough fast tanh: 2 MUFU (EX2 + RCP) + a few FMA. Avoids
// tanh.approx.f32's ~5e-4 abs error which could threaten rel_err<1e-3.
__device__ __forceinline__ float tanh_fast(float x) {
    x = fminf(15.0f, fmaxf(-15.0f, x));
    float e = __expf(2.0f * x);
    return (e - 1.0f) * __fdividef(1.0f, e + 1.0f);
}

// Pass 2: 4 output pixels per thread (amortizes the 12 constant LDG.128,
// makes gray reads float4 and output writes float4).
__global__ void __launch_bounds__(256) k_main(float* __restrict__ out) {
    int idx = blockIdx.x * blockDim.x + threadIdx.x;   // quad index
    int wq  = idx & 63;            // 64 quads per output row
    int h   = (idx >> 6) & 255;
    int b   = idx >> 14;

    float4 cc[12];
    #pragma unroll
    for (int i = 0; i < 12; i++)
        cc[i] = reinterpret_cast<const float4*>(g_c)[i];
    const float* gc = reinterpret_cast<const float*>(cc);
    float A = gc[44], Bc = gc[45];

    const float4* gr = reinterpret_cast<const float4*>(g_gray + (size_t)b * N_HW + (size_t)(2 * h) * N_W);
    float4 a0 = gr[2 * wq],             a1 = gr[2 * wq + 1];
    float4 b0 = gr[2 * wq + N_W / 4],   b1 = gr[2 * wq + 1 + N_W / 4];

    // patch layout per output pixel: {g[2h][2w], g[2h][2w+1], g[2h+1][2w], g[2h+1][2w+1]}
    float px[4][4] = {
        {a0.x, a0.y, b0.x, b0.y},
        {a0.z, a0.w, b0.z, b0.w},
        {a1.x, a1.y, b1.x, b1.y},
        {a1.z, a1.w, b1.z, b1.w}};

    float res[4][4];   // [o][pixel]
    #pragma unroll
    for (int j = 0; j < 4; j++) {
        float e[4];
        #pragma unroll
        for (int q = 0; q < 4; q++)
            e[q] = __sinf(fmaf(px[j][q], A, Bc));
        #pragma unroll
        for (int l = 0; l < 2; l++) {
            float m[4];
            #pragma unroll
            for (int q = 0; q < 4; q++)
                m[q] = fmaf(e[q], gc[l * 4 + q],
                       fmaf(e[(q + 1) & 3], gc[8 + l * 4 + q], gc[16 + l * 4 + q]));
            #pragma unroll
            for (int q = 0; q < 4; q++)
                e[q] = tanh_fast(m[q]);
        }
        #pragma unroll
        for (int o = 0; o < 4; o++)
            res[o][j] = fmaf(e[3], gc[24 + o * 4 + 3],
                        fmaf(e[2], gc[24 + o * 4 + 2],
                        fmaf(e[1], gc[24 + o * 4 + 1],
                        fmaf(e[0], gc[24 + o * 4 + 0], gc[40 + o]))));
    }

    size_t ob = (size_t)(b * 4) * O_HW + (size_t)h * O_W + (size_t)(wq * 4);
    #pragma unroll
    for (int o = 0; o < 4; o++)
        *reinterpret_cast<float4*>(out + ob + (size_t)o * O_HW) =
            make_float4(res[o][0], res[o][1], res[o][2], res[o][3]);
}

extern "C" void kernel_launch(void* const* d_in, const int* in_sizes, int n_in,
                              void* d_out, int out_size) {
    const float* x  = (const float*)d_in[0];   // (64,3,512,512)
    const float* w  = (const float*)d_in[1];   // (2,4,3)
    const float* pw = (const float*)d_in[2];   // (4,4,1,1)
    const float* pb = (const float*)d_in[3];   // (4,)
    float* out = (float*)d_out;                // (64,4,256,256)

    k_init<<<1, 32>>>(w, pw, pb);
    k_gray<<<16384, 256>>>(x);                 // 64*512*512/4 threads
    k_norm<<<1, 1>>>();
    k_main<<<4096, 256>>>(out);                // 64*256*256/4 threads
}

// round 5
// speedup vs baseline: 1.0503x; 1.0343x over previous
#include <cuda_runtime.h>
#include <cuda_fp16.h>

#define N_HW  262144      // 512*512
#define N_W   512
#define O_HW  65536       // 256*256
#define O_W   256
#define PI_F  3.14159265358979f

// 32 MB fp16 scratch for the grayscale image.
__device__ __align__(32) __half g_grayh[(size_t)64 * N_HW];
__device__ unsigned g_min_ord, g_max_ord;
// packed constants:
// [0..7] cos(w[l][q][0]) (l*4+q); [8..15] sin(w[l][q][1]); [16..23] w[l][q][2]
// [24..39] proj_w[o][q]; [40..43] proj_b[o]; [44]=PI/range; [45]=-min*PI/range
__device__ float g_c[48];

// 32-byte vector view
union U32B {
    ulonglong4 v;
    float      f[8];
    __half2    h2[8];
    unsigned   u[8];
};

// ---- 32B cache-hinted memory helpers (sm_103a requires .v4.b64 for hints) --
__device__ __forceinline__ ulonglong4 ldg32_ef(const void* p) {  // read-once
    ulonglong4 v;
    asm("ld.global.nc.L2::evict_first.v4.b64 {%0,%1,%2,%3},[%4];"
        : "=l"(v.x), "=l"(v.y), "=l"(v.z), "=l"(v.w) : "l"(p));
    return v;
}
__device__ __forceinline__ void stg32_el(void* p, ulonglong4 v) {  // keep in L2
    asm volatile("st.global.L2::evict_last.v4.b64 [%0],{%1,%2,%3,%4};"
                 :: "l"(p), "l"(v.x), "l"(v.y), "l"(v.z), "l"(v.w));
}
__device__ __forceinline__ void stg32_ef(void* p, ulonglong4 v) {  // write-once
    asm volatile("st.global.L2::evict_first.v4.b64 [%0],{%1,%2,%3,%4};"
                 :: "l"(p), "l"(v.x), "l"(v.y), "l"(v.z), "l"(v.w));
}

__device__ __forceinline__ unsigned f2ord(float f) {
    unsigned u = __float_as_uint(f);
    return (u & 0x80000000u) ? ~u : (u | 0x80000000u);
}
__device__ __forceinline__ float ord2f(unsigned o) {
    unsigned u = (o & 0x80000000u) ? (o & 0x7fffffffu) : ~o;
    return __uint_as_float(u);
}

__global__ void k_init(const float* __restrict__ w,
                       const float* __restrict__ pw,
                       const float* __restrict__ pb) {
    int t = threadIdx.x;
    if (t == 0) { g_min_ord = 0xffffffffu; g_max_ord = 0u; }
    if (t < 8) {
        int l = t >> 2, q = t & 3;
        const float* wi = w + l * 12 + q * 3;
        g_c[t]      = cosf(wi[0]);
        g_c[8 + t]  = sinf(wi[1]);
        g_c[16 + t] = wi[2];
    }
    if (t < 16) g_c[24 + t] = pw[t];
    if (t < 4)  g_c[40 + t] = pb[t];
}

// Pass 1: gray = mean(channels) -> fp16 (L2-resident) + global min/max.
// 16 gray pixels per thread: 6x 32B loads, 1x 32B store.
__global__ void __launch_bounds__(256) k_gray(const float* __restrict__ x) {
    int idx = blockIdx.x * blockDim.x + threadIdx.x;   // 16-float group index
    int b   = idx >> 14;                               // 16384 groups per image
    int r   = idx & 16383;
    const char* xb = (const char*)(x + (size_t)b * (3 * N_HW) + (size_t)r * 16);
    U32B a0, a1, c0, c1, d0, d1;
    a0.v = ldg32_ef(xb);                  a1.v = ldg32_ef(xb + 32);
    c0.v = ldg32_ef(xb + N_HW * 4);       c1.v = ldg32_ef(xb + N_HW * 4 + 32);
    d0.v = ldg32_ef(xb + N_HW * 8);       d1.v = ldg32_ef(xb + N_HW * 8 + 32);
    const float k = 1.0f / 3.0f;
    float g[16];
    #pragma unroll
    for (int i = 0; i < 8; i++) {
        g[i]     = (a0.f[i] + c0.f[i] + d0.f[i]) * k;
        g[8 + i] = (a1.f[i] + c1.f[i] + d1.f[i]) * k;
    }
    U32B pk;
    #pragma unroll
    for (int i = 0; i < 8; i++)
        pk.h2[i] = __floats2half2_rn(g[2 * i], g[2 * i + 1]);
    stg32_el((char*)g_grayh + (size_t)idx * 32, pk.v);

    float lmin = g[0], lmax = g[0];
    #pragma unroll
    for (int i = 1; i < 16; i++) { lmin = fminf(lmin, g[i]); lmax = fmaxf(lmax, g[i]); }
    #pragma unroll
    for (int off = 16; off > 0; off >>= 1) {
        lmin = fminf(lmin, __shfl_xor_sync(0xffffffffu, lmin, off));
        lmax = fmaxf(lmax, __shfl_xor_sync(0xffffffffu, lmax, off));
    }
    __shared__ float smin[8], smax[8];
    int lane = threadIdx.x & 31, wid = threadIdx.x >> 5;
    if (lane == 0) { smin[wid] = lmin; smax[wid] = lmax; }
    __syncthreads();
    if (wid == 0) {
        lmin = (lane < 8) ? smin[lane] : __uint_as_float(0x7f800000u);
        lmax = (lane < 8) ? smax[lane] : __uint_as_float(0xff800000u);
        #pragma unroll
        for (int off = 4; off > 0; off >>= 1) {
            lmin = fminf(lmin, __shfl_xor_sync(0xffffffffu, lmin, off));
            lmax = fmaxf(lmax, __shfl_xor_sync(0xffffffffu, lmax, off));
        }
        if (lane == 0) {
            atomicMin(&g_min_ord, f2ord(lmin));
            atomicMax(&g_max_ord, f2ord(lmax));
        }
    }
}

__global__ void k_norm() {
    float mn  = ord2f(g_min_ord);
    float mx  = ord2f(g_max_ord);
    float inv = 1.0f / (mx - mn + 1e-8f);
    g_c[44] = inv * PI_F;
    g_c[45] = -mn * inv * PI_F;
}

// layer-2 tanh: exact-enough (EX2 + RCP)
__device__ __forceinline__ float tanh_fast(float x) {
    x = fminf(15.0f, fmaxf(-15.0f, x));
    float e = __expf(2.0f * x);
    return (e - 1.0f) * __fdividef(1.0f, e + 1.0f);
}
// layer-1 tanh: single-MUFU approx; error damped by accurate layer-2 tanh
__device__ __forceinline__ float tanh_apx(float x) {
    float y;
    asm("tanh.approx.f32 %0, %1;" : "=f"(y) : "f"(x));
    return y;
}

// Pass 2: 8 output pixels per thread; gray reads should hit L2.
__global__ void __launch_bounds__(256) k_main(float* __restrict__ out) {
    int idx = blockIdx.x * blockDim.x + threadIdx.x;   // 8-pixel group index
    int wq  = idx & 31;            // 32 groups per output row
    int h   = (idx >> 5) & 255;
    int b   = idx >> 13;

    float4 cc[12];
    #pragma unroll
    for (int i = 0; i < 12; i++)
        cc[i] = reinterpret_cast<const float4*>(g_c)[i];
    const float* gc = reinterpret_cast<const float*>(cc);
    float A = gc[44], Bc = gc[45];

    // gray rows 2h, 2h+1; 16 halves (32B) per group; row stride = 1024B
    const char* gr = (const char*)(g_grayh + (size_t)b * N_HW + (size_t)(2 * h) * N_W) + wq * 32;
    U32B r0, r1;
    r0.v = ldg32_ef(gr);
    r1.v = ldg32_ef(gr + N_W * 2);

    float f0[16], f1[16];
    #pragma unroll
    for (int i = 0; i < 8; i++) {
        float2 u = __half22float2(r0.h2[i]); f0[2*i] = u.x; f0[2*i+1] = u.y;
        float2 v = __half22float2(r1.h2[i]); f1[2*i] = v.x; f1[2*i+1] = v.y;
    }

    float res[4][8];   // [o][pixel]
    #pragma unroll
    for (int j = 0; j < 8; j++) {
        // patch: {g[2h][2w], g[2h][2w+1], g[2h+1][2w], g[2h+1][2w+1]}, w = 8*wq+j
        float px[4] = {f0[2*j], f0[2*j+1], f1[2*j], f1[2*j+1]};
        float e[4];
        #pragma unroll
        for (int q = 0; q < 4; q++)
            e[q] = __sinf(fmaf(px[q], A, Bc));
        // layer 0 (approx tanh)
        {
            float m[4];
            #pragma unroll
            for (int q = 0; q < 4; q++)
                m[q] = fmaf(e[q], gc[q], fmaf(e[(q + 1) & 3], gc[8 + q], gc[16 + q]));
            #pragma unroll
            for (int q = 0; q < 4; q++)
                e[q] = tanh_apx(m[q]);
        }
        // layer 1 (accurate tanh)
        {
            float m[4];
            #pragma unroll
            for (int q = 0; q < 4; q++)
                m[q] = fmaf(e[q], gc[4 + q], fmaf(e[(q + 1) & 3], gc[12 + q], gc[20 + q]));
            #pragma unroll
            for (int q = 0; q < 4; q++)
                e[q] = tanh_fast(m[q]);
        }
        #pragma unroll
        for (int o = 0; o < 4; o++)
            res[o][j] = fmaf(e[3], gc[24 + o * 4 + 3],
                        fmaf(e[2], gc[24 + o * 4 + 2],
                        fmaf(e[1], gc[24 + o * 4 + 1],
                        fmaf(e[0], gc[24 + o * 4 + 0], gc[40 + o]))));
    }

    size_t ob = (size_t)(b * 4) * O_HW + (size_t)h * O_W + (size_t)(wq * 8);
    #pragma unroll
    for (int o = 0; o < 4; o++) {
        U32B s;
        #pragma unroll
        for (int j = 0; j < 8; j++) s.f[j] = res[o][j];
        stg32_ef(out + ob + (size_t)o * O_HW, s.v);
    }
}

extern "C" void kernel_launch(void* const* d_in, const int* in_sizes, int n_in,
                              void* d_out, int out_size) {
    const float* x  = (const float*)d_in[0];   // (64,3,512,512)
    const float* w  = (const float*)d_in[1];   // (2,4,3)
    const float* pw = (const float*)d_in[2];   // (4,4,1,1)
    const float* pb = (const float*)d_in[3];   // (4,)
    float* out = (float*)d_out;                // (64,4,256,256)

    k_init<<<1, 32>>>(w, pw, pb);
    k_gray<<<4096, 256>>>(x);                  // 64*512*512/16 threads
    k_norm<<<1, 1>>>();
    k_main<<<2048, 256>>>(out);                // 64*256*256/8 threads
}

// round 6
// speedup vs baseline: 1.0782x; 1.0265x over previous
#include <cuda_runtime.h>
#include <cuda_fp16.h>

#define N_HW  262144      // 512*512
#define N_W   512
#define O_HW  65536       // 256*256
#define O_W   256
#define PI_F  3.14159265358979f

// 32 MB fp16 scratch for the grayscale image.
__device__ __align__(32) __half g_grayh[(size_t)64 * N_HW];
__device__ unsigned g_min_ord, g_max_ord;
// packed constants:
// [0..7] cos(w[l][q][0]) (l*4+q); [8..15] sin(w[l][q][1]); [16..23] w[l][q][2]
// [24..39] proj_w[o][q]; [40..43] proj_b[o]; [44]=PI/range; [45]=-min*PI/range
__device__ float g_c[48];

// 32-byte vector view
union U32B {
    ulonglong4 v;
    float      f[8];
    __half2    h2[8];
    unsigned   u[8];
};

// ---- 32B cache-hinted helpers (sm_103a: hints require .v4.b64 width) -------
__device__ __forceinline__ ulonglong4 ldg32_ef(const void* p) {  // read-once
    ulonglong4 v;
    asm("ld.global.nc.L2::evict_first.v4.b64 {%0,%1,%2,%3},[%4];"
        : "=l"(v.x), "=l"(v.y), "=l"(v.z), "=l"(v.w) : "l"(p));
    return v;
}
__device__ __forceinline__ void stg32_el(void* p, ulonglong4 v) {  // keep in L2
    asm volatile("st.global.L2::evict_last.v4.b64 [%0],{%1,%2,%3,%4};"
                 :: "l"(p), "l"(v.x), "l"(v.y), "l"(v.z), "l"(v.w));
}
__device__ __forceinline__ void stg32_ef(void* p, ulonglong4 v) {  // write-once
    asm volatile("st.global.L2::evict_first.v4.b64 [%0],{%1,%2,%3,%4};"
                 :: "l"(p), "l"(v.x), "l"(v.y), "l"(v.z), "l"(v.w));
}

__device__ __forceinline__ unsigned f2ord(float f) {
    unsigned u = __float_as_uint(f);
    return (u & 0x80000000u) ? ~u : (u | 0x80000000u);
}
__device__ __forceinline__ float ord2f(unsigned o) {
    unsigned u = (o & 0x80000000u) ? (o & 0x7fffffffu) : ~o;
    return __uint_as_float(u);
}

__global__ void k_init(const float* __restrict__ w,
                       const float* __restrict__ pw,
                       const float* __restrict__ pb) {
    int t = threadIdx.x;
    if (t == 0) { g_min_ord = 0xffffffffu; g_max_ord = 0u; }
    if (t < 8) {
        int l = t >> 2, q = t & 3;
        const float* wi = w + l * 12 + q * 3;
        g_c[t]      = cosf(wi[0]);
        g_c[8 + t]  = sinf(wi[1]);
        g_c[16 + t] = wi[2];
    }
    if (t < 16) g_c[24 + t] = pw[t];
    if (t < 4)  g_c[40 + t] = pb[t];
}

// Pass 1: gray = mean(channels) -> fp16 (L2-resident) + global min/max.
// 16 gray pixels/thread: 12x plain __ldg float4 (proven-fast read path),
// 1x 32B evict_last store.
__global__ void __launch_bounds__(256) k_gray(const float* __restrict__ x) {
    int idx = blockIdx.x * blockDim.x + threadIdx.x;   // 16-float group index
    int b   = idx >> 14;                               // 16384 groups per image
    int r   = idx & 16383;
    const float4* xb = reinterpret_cast<const float4*>(x + (size_t)b * (3 * N_HW)) + 4 * r;
    float4 va[4], vc[4], vd[4];
    #pragma unroll
    for (int i = 0; i < 4; i++) va[i] = __ldg(xb + i);
    #pragma unroll
    for (int i = 0; i < 4; i++) vc[i] = __ldg(xb + N_HW / 4 + i);
    #pragma unroll
    for (int i = 0; i < 4; i++) vd[i] = __ldg(xb + N_HW / 2 + i);

    const float k = 1.0f / 3.0f;
    float g[16];
    #pragma unroll
    for (int i = 0; i < 4; i++) {
        g[4*i+0] = (va[i].x + vc[i].x + vd[i].x) * k;
        g[4*i+1] = (va[i].y + vc[i].y + vd[i].y) * k;
        g[4*i+2] = (va[i].z + vc[i].z + vd[i].z) * k;
        g[4*i+3] = (va[i].w + vc[i].w + vd[i].w) * k;
    }
    U32B pk;
    #pragma unroll
    for (int i = 0; i < 8; i++)
        pk.h2[i] = __floats2half2_rn(g[2 * i], g[2 * i + 1]);
    stg32_el((char*)g_grayh + (size_t)idx * 32, pk.v);

    float lmin = g[0], lmax = g[0];
    #pragma unroll
    for (int i = 1; i < 16; i++) { lmin = fminf(lmin, g[i]); lmax = fmaxf(lmax, g[i]); }
    #pragma unroll
    for (int off = 16; off > 0; off >>= 1) {
        lmin = fminf(lmin, __shfl_xor_sync(0xffffffffu, lmin, off));
        lmax = fmaxf(lmax, __shfl_xor_sync(0xffffffffu, lmax, off));
    }
    __shared__ float smin[8], smax[8];
    int lane = threadIdx.x & 31, wid = threadIdx.x >> 5;
    if (lane == 0) { smin[wid] = lmin; smax[wid] = lmax; }
    __syncthreads();
    if (wid == 0) {
        lmin = (lane < 8) ? smin[lane] : __uint_as_float(0x7f800000u);
        lmax = (lane < 8) ? smax[lane] : __uint_as_float(0xff800000u);
        #pragma unroll
        for (int off = 4; off > 0; off >>= 1) {
            lmin = fminf(lmin, __shfl_xor_sync(0xffffffffu, lmin, off));
            lmax = fmaxf(lmax, __shfl_xor_sync(0xffffffffu, lmax, off));
        }
        if (lane == 0) {
            atomicMin(&g_min_ord, f2ord(lmin));
            atomicMax(&g_max_ord, f2ord(lmax));
        }
    }
}

__global__ void k_norm() {
    float mn  = ord2f(g_min_ord);
    float mx  = ord2f(g_max_ord);
    float inv = 1.0f / (mx - mn + 1e-8f);
    g_c[44] = inv * PI_F;
    g_c[45] = -mn * inv * PI_F;
}

// single-MUFU tanh approx (both layers; error ~1e-4 RMS at output, inside 1e-3)
__device__ __forceinline__ float tanh_apx(float x) {
    float y;
    asm("tanh.approx.f32 %0, %1;" : "=f"(y) : "f"(x));
    return y;
}

// Pass 2: 8 output pixels per thread; gray reads hit L2 (evict_last from pass 1).
__global__ void __launch_bounds__(256) k_main(float* __restrict__ out) {
    int idx = blockIdx.x * blockDim.x + threadIdx.x;   // 8-pixel group index
    int wq  = idx & 31;            // 32 groups per output row
    int h   = (idx >> 5) & 255;
    int b   = idx >> 13;

    float4 cc[12];
    #pragma unroll
    for (int i = 0; i < 12; i++)
        cc[i] = reinterpret_cast<const float4*>(g_c)[i];
    const float* gc = reinterpret_cast<const float*>(cc);
    float A = gc[44], Bc = gc[45];

    // gray rows 2h, 2h+1; 16 halves (32B) per group; row stride = 1024B
    const char* gr = (const char*)(g_grayh + (size_t)b * N_HW + (size_t)(2 * h) * N_W) + wq * 32;
    U32B r0, r1;
    r0.v = ldg32_ef(gr);
    r1.v = ldg32_ef(gr + N_W * 2);

    float f0[16], f1[16];
    #pragma unroll
    for (int i = 0; i < 8; i++) {
        float2 u = __half22float2(r0.h2[i]); f0[2*i] = u.x; f0[2*i+1] = u.y;
        float2 v = __half22float2(r1.h2[i]); f1[2*i] = v.x; f1[2*i+1] = v.y;
    }

    float res[4][8];   // [o][pixel]
    #pragma unroll
    for (int j = 0; j < 8; j++) {
        // patch: {g[2h][2w], g[2h][2w+1], g[2h+1][2w], g[2h+1][2w+1]}, w = 8*wq+j
        float px[4] = {f0[2*j], f0[2*j+1], f1[2*j], f1[2*j+1]};
        float e[4];
        #pragma unroll
        for (int q = 0; q < 4; q++)
            e[q] = __sinf(fmaf(px[q], A, Bc));
        #pragma unroll
        for (int l = 0; l < 2; l++) {
            float m[4];
            #pragma unroll
            for (int q = 0; q < 4; q++)
                m[q] = fmaf(e[q], gc[l * 4 + q],
                       fmaf(e[(q + 1) & 3], gc[8 + l * 4 + q], gc[16 + l * 4 + q]));
            #pragma unroll
            for (int q = 0; q < 4; q++)
                e[q] = tanh_apx(m[q]);
        }
        #pragma unroll
        for (int o = 0; o < 4; o++)
            res[o][j] = fmaf(e[3], gc[24 + o * 4 + 3],
                        fmaf(e[2], gc[24 + o * 4 + 2],
                        fmaf(e[1], gc[24 + o * 4 + 1],
                        fmaf(e[0], gc[24 + o * 4 + 0], gc[40 + o]))));
    }

    size_t ob = (size_t)(b * 4) * O_HW + (size_t)h * O_W + (size_t)(wq * 8);
    #pragma unroll
    for (int o = 0; o < 4; o++) {
        U32B s;
        #pragma unroll
        for (int j = 0; j < 8; j++) s.f[j] = res[o][j];
        stg32_ef(out + ob + (size_t)o * O_HW, s.v);
    }
}

extern "C" void kernel_launch(void* const* d_in, const int* in_sizes, int n_in,
                              void* d_out, int out_size) {
    const float* x  = (const float*)d_in[0];   // (64,3,512,512)
    const float* w  = (const float*)d_in[1];   // (2,4,3)
    const float* pw = (const float*)d_in[2];   // (4,4,1,1)
    const float* pb = (const float*)d_in[3];   // (4,)
    float* out = (float*)d_out;                // (64,4,256,256)

    k_init<<<1, 32>>>(w, pw, pb);
    k_gray<<<4096, 256>>>(x);                  // 64*512*512/16 threads
    k_norm<<<1, 1>>>();
    k_main<<<2048, 256>>>(out);                // 64*256*256/8 threads
}

// round 7
// speedup vs baseline: 1.1991x; 1.1122x over previous
#include <cuda_runtime.h>
#include <cuda_fp16.h>

#define N_HW  262144      // 512*512
#define N_W   512
#define O_HW  65536       // 256*256
#define O_W   256
#define PI_F  3.14159265358979f

// 32 MB fp16 scratch for the grayscale image.
__device__ __align__(32) __half g_grayh[(size_t)64 * N_HW];
__device__ unsigned g_min_ord, g_max_ord;
// packed constants:
// [0..7] cos(w[l][q][0]) (l*4+q); [8..15] sin(w[l][q][1]); [16..23] w[l][q][2]
// [24..39] proj_w[o][q]; [40..43] proj_b[o]; [44]=PI/range; [45]=-min*PI/range
__device__ float g_c[48];

// 32-byte / 16-byte vector views
union U32B {
    ulonglong4 v;
    float      f[8];
    __half2    h2[8];
};
union U16B {
    uint4   v;
    __half2 h2[4];
};

// 32B evict_first load (sm_103a: L2 hints require .v4.b64 width)
__device__ __forceinline__ ulonglong4 ldg32_ef(const void* p) {
    ulonglong4 v;
    asm("ld.global.nc.L2::evict_first.v4.b64 {%0,%1,%2,%3},[%4];"
        : "=l"(v.x), "=l"(v.y), "=l"(v.z), "=l"(v.w) : "l"(p));
    return v;
}

__device__ __forceinline__ unsigned f2ord(float f) {
    unsigned u = __float_as_uint(f);
    return (u & 0x80000000u) ? ~u : (u | 0x80000000u);
}
__device__ __forceinline__ float ord2f(unsigned o) {
    unsigned u = (o & 0x80000000u) ? (o & 0x7fffffffu) : ~o;
    return __uint_as_float(u);
}

__global__ void k_init(const float* __restrict__ w,
                       const float* __restrict__ pw,
                       const float* __restrict__ pb) {
    int t = threadIdx.x;
    if (t == 0) { g_min_ord = 0xffffffffu; g_max_ord = 0u; }
    if (t < 8) {
        int l = t >> 2, q = t & 3;
        const float* wi = w + l * 12 + q * 3;
        g_c[t]      = cosf(wi[0]);
        g_c[8 + t]  = sinf(wi[1]);
        g_c[16 + t] = wi[2];
    }
    if (t < 16) g_c[24 + t] = pw[t];
    if (t < 4)  g_c[40 + t] = pb[t];
}

// Pass 1: gray = mean(channels) -> fp16 (stays in L2) + global min/max.
// 8 gray pixels/thread: exactly 3 LDG (32B evict_first, one per channel) —
// low MLP_p1 to avoid cross-CTA L1tex-queue contention (R2 evidence),
// and evict_first keeps the 201MB x stream from evicting gray in L2.
__global__ void __launch_bounds__(256) k_gray(const float* __restrict__ x) {
    int idx = blockIdx.x * blockDim.x + threadIdx.x;   // 8-float group index
    int b   = idx >> 15;                               // 32768 groups per image
    int r   = idx & 32767;
    const float* xb = x + (size_t)b * (3 * N_HW) + (size_t)r * 8;
    U32B va, vc, vd;
    va.v = ldg32_ef(xb);
    vc.v = ldg32_ef(xb + N_HW);
    vd.v = ldg32_ef(xb + 2 * N_HW);

    const float k = 1.0f / 3.0f;
    float g[8];
    #pragma unroll
    for (int i = 0; i < 8; i++)
        g[i] = (va.f[i] + vc.f[i] + vd.f[i]) * k;

    U16B pk;
    #pragma unroll
    for (int i = 0; i < 4; i++)
        pk.h2[i] = __floats2half2_rn(g[2 * i], g[2 * i + 1]);
    reinterpret_cast<uint4*>(g_grayh)[idx] = pk.v;     // plain store, L2-resident

    float lmin = g[0], lmax = g[0];
    #pragma unroll
    for (int i = 1; i < 8; i++) { lmin = fminf(lmin, g[i]); lmax = fmaxf(lmax, g[i]); }
    #pragma unroll
    for (int off = 16; off > 0; off >>= 1) {
        lmin = fminf(lmin, __shfl_xor_sync(0xffffffffu, lmin, off));
        lmax = fmaxf(lmax, __shfl_xor_sync(0xffffffffu, lmax, off));
    }
    __shared__ float smin[8], smax[8];
    int lane = threadIdx.x & 31, wid = threadIdx.x >> 5;
    if (lane == 0) { smin[wid] = lmin; smax[wid] = lmax; }
    __syncthreads();
    if (wid == 0) {
        lmin = (lane < 8) ? smin[lane] : __uint_as_float(0x7f800000u);
        lmax = (lane < 8) ? smax[lane] : __uint_as_float(0xff800000u);
        #pragma unroll
        for (int off = 4; off > 0; off >>= 1) {
            lmin = fminf(lmin, __shfl_xor_sync(0xffffffffu, lmin, off));
            lmax = fmaxf(lmax, __shfl_xor_sync(0xffffffffu, lmax, off));
        }
        if (lane == 0) {
            atomicMin(&g_min_ord, f2ord(lmin));
            atomicMax(&g_max_ord, f2ord(lmax));
        }
    }
}

__global__ void k_norm() {
    float mn  = ord2f(g_min_ord);
    float mx  = ord2f(g_max_ord);
    float inv = 1.0f / (mx - mn + 1e-8f);
    g_c[44] = inv * PI_F;
    g_c[45] = -mn * inv * PI_F;
}

// single-MUFU tanh approx (both layers; measured output rel_err ~6e-5)
__device__ __forceinline__ float tanh_apx(float x) {
    float y;
    asm("tanh.approx.f32 %0, %1;" : "=f"(y) : "f"(x));
    return y;
}

// Pass 2: 4 output pixels/thread (48-reg shape, occ ~54%); gray reads hit L2.
__global__ void __launch_bounds__(256) k_main(float* __restrict__ out) {
    int idx = blockIdx.x * blockDim.x + threadIdx.x;   // quad index
    int wq  = idx & 63;            // 64 quads per output row
    int h   = (idx >> 6) & 255;
    int b   = idx >> 14;

    float4 cc[12];
    #pragma unroll
    for (int i = 0; i < 12; i++)
        cc[i] = reinterpret_cast<const float4*>(g_c)[i];
    const float* gc = reinterpret_cast<const float*>(cc);
    float A = gc[44], Bc = gc[45];

    // gray rows 2h, 2h+1; 8 halves (16B) per quad; row = 64 uint4
    const uint4* gr = reinterpret_cast<const uint4*>(
        g_grayh + (size_t)b * N_HW + (size_t)(2 * h) * N_W) + wq;
    U16B r0, r1;
    r0.v = __ldg(gr);
    r1.v = __ldg(gr + 64);

    float f0[8], f1[8];
    #pragma unroll
    for (int i = 0; i < 4; i++) {
        float2 u = __half22float2(r0.h2[i]); f0[2*i] = u.x; f0[2*i+1] = u.y;
        float2 v = __half22float2(r1.h2[i]); f1[2*i] = v.x; f1[2*i+1] = v.y;
    }

    float res[4][4];   // [o][pixel]
    #pragma unroll
    for (int j = 0; j < 4; j++) {
        // patch: {g[2h][2w], g[2h][2w+1], g[2h+1][2w], g[2h+1][2w+1]}, w = 4*wq+j
        float px[4] = {f0[2*j], f0[2*j+1], f1[2*j], f1[2*j+1]};
        float e[4];
        #pragma unroll
        for (int q = 0; q < 4; q++)
            e[q] = __sinf(fmaf(px[q], A, Bc));
        #pragma unroll
        for (int l = 0; l < 2; l++) {
            float m[4];
            #pragma unroll
            for (int q = 0; q < 4; q++)
                m[q] = fmaf(e[q], gc[l * 4 + q],
                       fmaf(e[(q + 1) & 3], gc[8 + l * 4 + q], gc[16 + l * 4 + q]));
            #pragma unroll
            for (int q = 0; q < 4; q++)
                e[q] = tanh_apx(m[q]);
        }
        #pragma unroll
        for (int o = 0; o < 4; o++)
            res[o][j] = fmaf(e[3], gc[24 + o * 4 + 3],
                        fmaf(e[2], gc[24 + o * 4 + 2],
                        fmaf(e[1], gc[24 + o * 4 + 1],
                        fmaf(e[0], gc[24 + o * 4 + 0], gc[40 + o]))));
    }

    size_t ob = (size_t)(b * 4) * O_HW + (size_t)h * O_W + (size_t)(wq * 4);
    #pragma unroll
    for (int o = 0; o < 4; o++)
        *reinterpret_cast<float4*>(out + ob + (size_t)o * O_HW) =
            make_float4(res[o][0], res[o][1], res[o][2], res[o][3]);
}

extern "C" void kernel_launch(void* const* d_in, const int* in_sizes, int n_in,
                              void* d_out, int out_size) {
    const float* x  = (const float*)d_in[0];   // (64,3,512,512)
    const float* w  = (const float*)d_in[1];   // (2,4,3)
    const float* pw = (const float*)d_in[2];   // (4,4,1,1)
    const float* pb = (const float*)d_in[3];   // (4,)
    float* out = (float*)d_out;                // (64,4,256,256)

    k_init<<<1, 32>>>(w, pw, pb);
    k_gray<<<8192, 256>>>(x);                  // 64*512*512/8 threads
    k_norm<<<1, 1>>>();
    k_main<<<4096, 256>>>(out);                // 64*256*256/4 threads
}

// round 8
// speedup vs baseline: 1.2228x; 1.0197x over previous
#include <cuda_runtime.h>
#include <cuda_fp16.h>

#define N_HW  262144      // 512*512
#define N_W   512
#define O_HW  65536       // 256*256
#define O_W   256
#define PI_F  3.14159265358979f

// 32 MB fp16 scratch for the grayscale image.
__device__ __align__(32) __half g_grayh[(size_t)64 * N_HW];
__device__ unsigned g_min_ord, g_max_ord;
// packed constants:
// [0..7] cos(w[l][q][0]) (l*4+q); [8..15] sin(w[l][q][1]); [16..23] w[l][q][2]
// [24..39] proj_w[o][q]; [40..43] proj_b[o]; [44]=PI/range; [45]=-min*PI/range
__device__ float g_c[48];

// 32-byte / 16-byte vector views
union U32B {
    ulonglong4 v;
    float      f[8];
    __half2    h2[8];
};
union U16B {
    uint4   v;
    __half2 h2[4];
};

// 32B evict_first load (sm_103a: L2 hints require .v4.b64 width)
__device__ __forceinline__ ulonglong4 ldg32_ef(const void* p) {
    ulonglong4 v;
    asm("ld.global.nc.L2::evict_first.v4.b64 {%0,%1,%2,%3},[%4];"
        : "=l"(v.x), "=l"(v.y), "=l"(v.z), "=l"(v.w) : "l"(p));
    return v;
}

__device__ __forceinline__ unsigned f2ord(float f) {
    unsigned u = __float_as_uint(f);
    return (u & 0x80000000u) ? ~u : (u | 0x80000000u);
}
__device__ __forceinline__ float ord2f(unsigned o) {
    unsigned u = (o & 0x80000000u) ? (o & 0x7fffffffu) : ~o;
    return __uint_as_float(u);
}

__global__ void k_init(const float* __restrict__ w,
                       const float* __restrict__ pw,
                       const float* __restrict__ pb) {
    int t = threadIdx.x;
    if (t == 0) { g_min_ord = 0xffffffffu; g_max_ord = 0u; }
    if (t < 8) {
        int l = t >> 2, q = t & 3;
        const float* wi = w + l * 12 + q * 3;
        g_c[t]      = cosf(wi[0]);
        g_c[8 + t]  = sinf(wi[1]);
        g_c[16 + t] = wi[2];
    }
    if (t < 16) g_c[24 + t] = pw[t];
    if (t < 4)  g_c[40 + t] = pb[t];
}

// Pass 1: gray = mean(channels) -> fp16 (stays in L2) + global min/max.
// 8 gray pixels/thread: exactly 3 LDG (32B evict_first, one per channel) —
// low MLP_p1 avoids cross-CTA L1tex-queue contention (R7-confirmed), and
// evict_first keeps the 201MB x stream from evicting gray in L2.
__global__ void __launch_bounds__(256) k_gray(const float* __restrict__ x) {
    int idx = blockIdx.x * blockDim.x + threadIdx.x;   // 8-float group index
    int b   = idx >> 15;                               // 32768 groups per image
    int r   = idx & 32767;
    const float* xb = x + (size_t)b * (3 * N_HW) + (size_t)r * 8;
    U32B va, vc, vd;
    va.v = ldg32_ef(xb);
    vc.v = ldg32_ef(xb + N_HW);
    vd.v = ldg32_ef(xb + 2 * N_HW);

    const float k = 1.0f / 3.0f;
    float g[8];
    #pragma unroll
    for (int i = 0; i < 8; i++)
        g[i] = (va.f[i] + vc.f[i] + vd.f[i]) * k;

    U16B pk;
    #pragma unroll
    for (int i = 0; i < 4; i++)
        pk.h2[i] = __floats2half2_rn(g[2 * i], g[2 * i + 1]);
    reinterpret_cast<uint4*>(g_grayh)[idx] = pk.v;     // plain store, L2-resident

    float lmin = g[0], lmax = g[0];
    #pragma unroll
    for (int i = 1; i < 8; i++) { lmin = fminf(lmin, g[i]); lmax = fmaxf(lmax, g[i]); }
    #pragma unroll
    for (int off = 16; off > 0; off >>= 1) {
        lmin = fminf(lmin, __shfl_xor_sync(0xffffffffu, lmin, off));
        lmax = fmaxf(lmax, __shfl_xor_sync(0xffffffffu, lmax, off));
    }
    __shared__ float smin[8], smax[8];
    int lane = threadIdx.x & 31, wid = threadIdx.x >> 5;
    if (lane == 0) { smin[wid] = lmin; smax[wid] = lmax; }
    __syncthreads();
    if (wid == 0) {
        lmin = (lane < 8) ? smin[lane] : __uint_as_float(0x7f800000u);
        lmax = (lane < 8) ? smax[lane] : __uint_as_float(0xff800000u);
        #pragma unroll
        for (int off = 4; off > 0; off >>= 1) {
            lmin = fminf(lmin, __shfl_xor_sync(0xffffffffu, lmin, off));
            lmax = fmaxf(lmax, __shfl_xor_sync(0xffffffffu, lmax, off));
        }
        if (lane == 0) {
            atomicMin(&g_min_ord, f2ord(lmin));
            atomicMax(&g_max_ord, f2ord(lmax));
        }
    }
}

__global__ void k_norm() {
    float mn  = ord2f(g_min_ord);
    float mx  = ord2f(g_max_ord);
    float inv = 1.0f / (mx - mn + 1e-8f);
    g_c[44] = inv * PI_F;
    g_c[45] = -mn * inv * PI_F;
}

// single-MUFU tanh approx (both layers; measured output rel_err ~6e-5)
__device__ __forceinline__ float tanh_apx(float x) {
    float y;
    asm("tanh.approx.f32 %0, %1;" : "=f"(y) : "f"(x));
    return y;
}

// Pass 2: 4 output pixels/thread; force 5 blocks/SM (<=48 regs) for 62.5% occ
// — R7 showed latency-bound at occ 42.5% / issue 50% with regs=53.
__global__ void __launch_bounds__(256, 5) k_main(float* __restrict__ out) {
    int idx = blockIdx.x * blockDim.x + threadIdx.x;   // quad index
    int wq  = idx & 63;            // 64 quads per output row
    int h   = (idx >> 6) & 255;
    int b   = idx >> 14;

    float4 cc[12];
    #pragma unroll
    for (int i = 0; i < 12; i++)
        cc[i] = reinterpret_cast<const float4*>(g_c)[i];
    const float* gc = reinterpret_cast<const float*>(cc);
    float A = gc[44], Bc = gc[45];

    // gray rows 2h, 2h+1; 8 halves (16B) per quad; row = 64 uint4
    const uint4* gr = reinterpret_cast<const uint4*>(
        g_grayh + (size_t)b * N_HW + (size_t)(2 * h) * N_W) + wq;
    U16B r0, r1;
    r0.v = __ldg(gr);
    r1.v = __ldg(gr + 64);

    float f0[8], f1[8];
    #pragma unroll
    for (int i = 0; i < 4; i++) {
        float2 u = __half22float2(r0.h2[i]); f0[2*i] = u.x; f0[2*i+1] = u.y;
        float2 v = __half22float2(r1.h2[i]); f1[2*i] = v.x; f1[2*i+1] = v.y;
    }

    float res[4][4];   // [o][pixel]
    #pragma unroll
    for (int j = 0; j < 4; j++) {
        // patch: {g[2h][2w], g[2h][2w+1], g[2h+1][2w], g[2h+1][2w+1]}, w = 4*wq+j
        float px[4] = {f0[2*j], f0[2*j+1], f1[2*j], f1[2*j+1]};
        float e[4];
        #pragma unroll
        for (int q = 0; q < 4; q++)
            e[q] = __sinf(fmaf(px[q], A, Bc));
        #pragma unroll
        for (int l = 0; l < 2; l++) {
            float m[4];
            #pragma unroll
            for (int q = 0; q < 4; q++)
                m[q] = fmaf(e[q], gc[l * 4 + q],
                       fmaf(e[(q + 1) & 3], gc[8 + l * 4 + q], gc[16 + l * 4 + q]));
            #pragma unroll
            for (int q = 0; q < 4; q++)
                e[q] = tanh_apx(m[q]);
        }
        #pragma unroll
        for (int o = 0; o < 4; o++)
            res[o][j] = fmaf(e[3], gc[24 + o * 4 + 3],
                        fmaf(e[2], gc[24 + o * 4 + 2],
                        fmaf(e[1], gc[24 + o * 4 + 1],
                        fmaf(e[0], gc[24 + o * 4 + 0], gc[40 + o]))));
    }

    size_t ob = (size_t)(b * 4) * O_HW + (size_t)h * O_W + (size_t)(wq * 4);
    #pragma unroll
    for (int o = 0; o < 4; o++)
        *reinterpret_cast<float4*>(out + ob + (size_t)o * O_HW) =
            make_float4(res[o][0], res[o][1], res[o][2], res[o][3]);
}

extern "C" void kernel_launch(void* const* d_in, const int* in_sizes, int n_in,
                              void* d_out, int out_size) {
    const float* x  = (const float*)d_in[0];   // (64,3,512,512)
    const float* w  = (const float*)d_in[1];   // (2,4,3)
    const float* pw = (const float*)d_in[2];   // (4,4,1,1)
    const float* pb = (const float*)d_in[3];   // (4,)
    float* out = (float*)d_out;                // (64,4,256,256)

    k_init<<<1, 32>>>(w, pw, pb);
    k_gray<<<8192, 256>>>(x);                  // 64*512*512/8 threads
    k_norm<<<1, 1>>>();
    k_main<<<4096, 256>>>(out);                // 64*256*256/4 threads
}

// round 9
// speedup vs baseline: 1.2241x; 1.0011x over previous
#include <cuda_runtime.h>
#include <cuda_fp16.h>

#define N_HW  262144      // 512*512
#define N_W   512
#define O_HW  65536       // 256*256
#define O_W   256
#define PI_F  3.14159265358979f

// 32 MB fp16 scratch for the grayscale image.
__device__ __align__(32) __half g_grayh[(size_t)64 * N_HW];
__device__ unsigned g_min_ord, g_max_ord;
// packed constants:
// [0..7] cos(w[l][q][0]) (l*4+q); [8..15] sin(w[l][q][1]); [16..23] w[l][q][2]
// [24..39] proj_w[o][q]; [40..43] proj_b[o]
__device__ float g_c[48];

// 32-byte / 16-byte vector views
union U32B {
    ulonglong4 v;
    float      f[8];
    __half2    h2[8];
};
union U16B {
    uint4   v;
    __half2 h2[4];
};

// 32B evict_first load (sm_103a: L2 hints require .v4.b64 width)
__device__ __forceinline__ ulonglong4 ldg32_ef(const void* p) {
    ulonglong4 v;
    asm("ld.global.nc.L2::evict_first.v4.b64 {%0,%1,%2,%3},[%4];"
        : "=l"(v.x), "=l"(v.y), "=l"(v.z), "=l"(v.w) : "l"(p));
    return v;
}

__device__ __forceinline__ unsigned f2ord(float f) {
    unsigned u = __float_as_uint(f);
    return (u & 0x80000000u) ? ~u : (u | 0x80000000u);
}
__device__ __forceinline__ float ord2f(unsigned o) {
    unsigned u = (o & 0x80000000u) ? (o & 0x7fffffffu) : ~o;
    return __uint_as_float(u);
}

__global__ void k_init(const float* __restrict__ w,
                       const float* __restrict__ pw,
                       const float* __restrict__ pb) {
    int t = threadIdx.x;
    if (t == 0) { g_min_ord = 0xffffffffu; g_max_ord = 0u; }
    if (t < 8) {
        int l = t >> 2, q = t & 3;
        const float* wi = w + l * 12 + q * 3;
        g_c[t]      = cosf(wi[0]);
        g_c[8 + t]  = sinf(wi[1]);
        g_c[16 + t] = wi[2];
    }
    if (t < 16) g_c[24 + t] = pw[t];
    if (t < 4)  g_c[40 + t] = pb[t];
}

// Pass 1: gray = mean(channels) -> fp16 (stays in L2) + global min/max.
// 8 gray pixels/thread: exactly 3 LDG (32B evict_first, one per channel) —
// low MLP_p1 avoids cross-CTA L1tex-queue contention (R7-confirmed), and
// evict_first keeps the 201MB x stream from evicting gray in L2.
__global__ void __launch_bounds__(256) k_gray(const float* __restrict__ x) {
    int idx = blockIdx.x * blockDim.x + threadIdx.x;   // 8-float group index
    int b   = idx >> 15;                               // 32768 groups per image
    int r   = idx & 32767;
    const float* xb = x + (size_t)b * (3 * N_HW) + (size_t)r * 8;
    U32B va, vc, vd;
    va.v = ldg32_ef(xb);
    vc.v = ldg32_ef(xb + N_HW);
    vd.v = ldg32_ef(xb + 2 * N_HW);

    const float k = 1.0f / 3.0f;
    float g[8];
    #pragma unroll
    for (int i = 0; i < 8; i++)
        g[i] = (va.f[i] + vc.f[i] + vd.f[i]) * k;

    U16B pk;
    #pragma unroll
    for (int i = 0; i < 4; i++)
        pk.h2[i] = __floats2half2_rn(g[2 * i], g[2 * i + 1]);
    reinterpret_cast<uint4*>(g_grayh)[idx] = pk.v;     // plain store, L2-resident

    float lmin = g[0], lmax = g[0];
    #pragma unroll
    for (int i = 1; i < 8; i++) { lmin = fminf(lmin, g[i]); lmax = fmaxf(lmax, g[i]); }
    #pragma unroll
    for (int off = 16; off > 0; off >>= 1) {
        lmin = fminf(lmin, __shfl_xor_sync(0xffffffffu, lmin, off));
        lmax = fmaxf(lmax, __shfl_xor_sync(0xffffffffu, lmax, off));
    }
    __shared__ float smin[8], smax[8];
    int lane = threadIdx.x & 31, wid = threadIdx.x >> 5;
    if (lane == 0) { smin[wid] = lmin; smax[wid] = lmax; }
    __syncthreads();
    if (wid == 0) {
        lmin = (lane < 8) ? smin[lane] : __uint_as_float(0x7f800000u);
        lmax = (lane < 8) ? smax[lane] : __uint_as_float(0xff800000u);
        #pragma unroll
        for (int off = 4; off > 0; off >>= 1) {
            lmin = fminf(lmin, __shfl_xor_sync(0xffffffffu, lmin, off));
            lmax = fmaxf(lmax, __shfl_xor_sync(0xffffffffu, lmax, off));
        }
        if (lane == 0) {
            atomicMin(&g_min_ord, f2ord(lmin));
            atomicMax(&g_max_ord, f2ord(lmax));
        }
    }
}

// single-MUFU tanh approx (both layers; measured output rel_err ~6e-5)
__device__ __forceinline__ float tanh_apx(float x) {
    float y;
    asm("tanh.approx.f32 %0, %1;" : "=f"(y) : "f"(x));
    return y;
}

// Pass 2: 4 output pixels/thread. Constants live in SMEM (one cooperative
// load per block) — removes the 12-LDG front batch that caused cross-CTA
// L1tex-queue contention and pinned regs at 48. k_norm folded in (thread 0).
__global__ void __launch_bounds__(256, 6) k_main(float* __restrict__ out) {
    __shared__ float sc[48];
    __shared__ float sAB[2];
    if (threadIdx.x < 48) sc[threadIdx.x] = g_c[threadIdx.x];
    if (threadIdx.x == 0) {
        float mn  = ord2f(g_min_ord);
        float mx  = ord2f(g_max_ord);
        float inv = __fdividef(PI_F, mx - mn + 1e-8f);
        sAB[0] = inv;
        sAB[1] = -mn * inv;
    }
    __syncthreads();

    int idx = blockIdx.x * blockDim.x + threadIdx.x;   // quad index
    int wq  = idx & 63;            // 64 quads per output row
    int h   = (idx >> 6) & 255;
    int b   = idx >> 14;

    float A = sAB[0], Bc = sAB[1];

    // gray rows 2h, 2h+1; 8 halves (16B) per quad; row = 64 uint4
    const uint4* gr = reinterpret_cast<const uint4*>(
        g_grayh + (size_t)b * N_HW + (size_t)(2 * h) * N_W) + wq;
    U16B r0, r1;
    r0.v = __ldg(gr);
    r1.v = __ldg(gr + 64);

    float f0[8], f1[8];
    #pragma unroll
    for (int i = 0; i < 4; i++) {
        float2 u = __half22float2(r0.h2[i]); f0[2*i] = u.x; f0[2*i+1] = u.y;
        float2 v = __half22float2(r1.h2[i]); f1[2*i] = v.x; f1[2*i+1] = v.y;
    }

    float res[4][4];   // [o][pixel]
    #pragma unroll
    for (int j = 0; j < 4; j++) {
        // patch: {g[2h][2w], g[2h][2w+1], g[2h+1][2w], g[2h+1][2w+1]}, w = 4*wq+j
        float px[4] = {f0[2*j], f0[2*j+1], f1[2*j], f1[2*j+1]};
        float e[4];
        #pragma unroll
        for (int q = 0; q < 4; q++)
            e[q] = __sinf(fmaf(px[q], A, Bc));
        #pragma unroll
        for (int l = 0; l < 2; l++) {
            float m[4];
            #pragma unroll
            for (int q = 0; q < 4; q++)
                m[q] = fmaf(e[q], sc[l * 4 + q],
                       fmaf(e[(q + 1) & 3], sc[8 + l * 4 + q], sc[16 + l * 4 + q]));
            #pragma unroll
            for (int q = 0; q < 4; q++)
                e[q] = tanh_apx(m[q]);
        }
        #pragma unroll
        for (int o = 0; o < 4; o++)
            res[o][j] = fmaf(e[3], sc[24 + o * 4 + 3],
                        fmaf(e[2], sc[24 + o * 4 + 2],
                        fmaf(e[1], sc[24 + o * 4 + 1],
                        fmaf(e[0], sc[24 + o * 4 + 0], sc[40 + o]))));
    }

    size_t ob = (size_t)(b * 4) * O_HW + (size_t)h * O_W + (size_t)(wq * 4);
    #pragma unroll
    for (int o = 0; o < 4; o++)
        *reinterpret_cast<float4*>(out + ob + (size_t)o * O_HW) =
            make_float4(res[o][0], res[o][1], res[o][2], res[o][3]);
}

extern "C" void kernel_launch(void* const* d_in, const int* in_sizes, int n_in,
                              void* d_out, int out_size) {
    const float* x  = (const float*)d_in[0];   // (64,3,512,512)
    const float* w  = (const float*)d_in[1];   // (2,4,3)
    const float* pw = (const float*)d_in[2];   // (4,4,1,1)
    const float* pb = (const float*)d_in[3];   // (4,)
    float* out = (float*)d_out;                // (64,4,256,256)

    k_init<<<1, 32>>>(w, pw, pb);
    k_gray<<<8192, 256>>>(x);                  // 64*512*512/8 threads
    k_main<<<4096, 256>>>(out);                // 64*256*256/4 threads
}